// round 16
// baseline (speedup 1.0000x reference)
#include <cuda_runtime.h>
#include <cuda_bf16.h>
#include <cuda_fp16.h>
#include <stdint.h>
#include <math.h>

#define BB 16
#define NN 1024
#define MM 1024
#define DD 512
#define NEGV (-2e20f)
#define NCHUNK 16

// ---- scratch (static device memory; ~96.3MB, proven envelope) ----
__device__ float g_S[(size_t)BB * NN * MM];     // 64 MB logits, then P in-place
__device__ float g_q2c[(size_t)BB * MM * DD];   // 32 MB
__device__ float g_s1[BB * NN];
__device__ float g_s2[BB * MM];
__device__ float g_rowM[BB * NN];
__device__ float g_rowIL[BB * NN];
__device__ float g_colM[BB * MM];
__device__ float g_colIL[BB * MM];
__device__ float g_pM[BB * NCHUNK * MM];
__device__ float g_pL[BB * NCHUNK * MM];

#define TILE_B 16384
extern __shared__ char dsm[];

__device__ __forceinline__ uint32_t swz(uint32_t off) { return off ^ ((off >> 3) & 0x70u); }

__device__ __forceinline__ void ldsm4(uint32_t addr, unsigned &r0, unsigned &r1,
                                      unsigned &r2, unsigned &r3)
{
    asm volatile("ldmatrix.sync.aligned.m8n8.x4.shared.b16 {%0,%1,%2,%3}, [%4];"
                 : "=r"(r0), "=r"(r1), "=r"(r2), "=r"(r3) : "r"(addr));
}

__device__ __forceinline__ void mmab(float* c, const unsigned* a, const unsigned* b)
{
    asm volatile("mma.sync.aligned.m16n8k16.row.col.f32.bf16.bf16.f32 "
                 "{%0,%1,%2,%3},{%4,%5,%6,%7},{%8,%9},{%0,%1,%2,%3};"
                 : "+f"(c[0]), "+f"(c[1]), "+f"(c[2]), "+f"(c[3])
                 : "r"(a[0]), "r"(a[1]), "r"(a[2]), "r"(a[3]), "r"(b[0]), "r"(b[1]));
}

__device__ __forceinline__ void mmah(float* c, const unsigned* a, const unsigned* b)
{
    asm volatile("mma.sync.aligned.m16n8k16.row.col.f32.f16.f16.f32 "
                 "{%0,%1,%2,%3},{%4,%5,%6,%7},{%8,%9},{%0,%1,%2,%3};"
                 : "+f"(c[0]), "+f"(c[1]), "+f"(c[2]), "+f"(c[3])
                 : "r"(a[0]), "r"(a[1]), "r"(a[2]), "r"(a[3]), "r"(b[0]), "r"(b[1]));
}

// ---- bf16 3-term split helpers (k_sim; BK=32) ----
__device__ __forceinline__ void store16(char* smp, int row, int cg, const float* v)
{
    unsigned h[8], l[8];
    #pragma unroll
    for (int i = 0; i < 8; i++) {
        float a = v[2*i], b = v[2*i+1];
        __nv_bfloat162 hb = __floats2bfloat162_rn(a, b);
        float2 hf = __bfloat1622float2(hb);
        __nv_bfloat162 lb = __floats2bfloat162_rn(a - hf.x, b - hf.y);
        h[i] = *(unsigned*)&hb;
        l[i] = *(unsigned*)&lb;
    }
    uint32_t base = (uint32_t)(row * 128 + cg * 2);
    *(uint4*)(smp + swz(base))      = make_uint4(h[0], h[1], h[2], h[3]);
    *(uint4*)(smp + swz(base + 16)) = make_uint4(h[4], h[5], h[6], h[7]);
    *(uint4*)(smp + swz(base + 64)) = make_uint4(l[0], l[1], l[2], l[3]);
    *(uint4*)(smp + swz(base + 80)) = make_uint4(l[4], l[5], l[6], l[7]);
}

__device__ __forceinline__ void mma_stage(uint32_t asu, uint32_t bsu, int wm, int wn,
                                          int lane, float (*acc)[4][4])
{
    #pragma unroll
    for (int kk = 0; kk < 32; kk += 16) {
        unsigned Ah[4][4], Al[4][4], Bh[4][2], Bl[4][2];
        uint32_t co = (uint32_t)((kk + ((lane >> 4) << 3)) * 2);
        #pragma unroll
        for (int im = 0; im < 4; im++) {
            uint32_t row = wm * 64 + im * 16 + (lane & 15);
            ldsm4(asu + swz(row * 128 + co),      Ah[im][0], Ah[im][1], Ah[im][2], Ah[im][3]);
            ldsm4(asu + swz(row * 128 + 64 + co), Al[im][0], Al[im][1], Al[im][2], Al[im][3]);
        }
        uint32_t cb = (uint32_t)((kk + (((lane >> 3) & 1) << 3)) * 2);
        #pragma unroll
        for (int p = 0; p < 2; p++) {
            uint32_t rb = wn * 32 + p * 16 + (lane & 7) + (((lane >> 4) & 1) << 3);
            ldsm4(bsu + swz(rb * 128 + cb),      Bh[2*p][0], Bh[2*p][1], Bh[2*p+1][0], Bh[2*p+1][1]);
            ldsm4(bsu + swz(rb * 128 + 64 + cb), Bl[2*p][0], Bl[2*p][1], Bl[2*p+1][0], Bl[2*p+1][1]);
        }
        #pragma unroll
        for (int im = 0; im < 4; im++)
            #pragma unroll
            for (int in = 0; in < 4; in++) {
                mmab(acc[im][in], Ah[im], Bh[in]);
                mmab(acc[im][in], Ah[im], Bl[in]);
                mmab(acc[im][in], Al[im], Bh[in]);
            }
    }
}

// ---- fp16 single-term helpers (BK=64; row = 64 fp16 = 128B) ----
__device__ __forceinline__ void store32h(char* smp, int row, int cg, const unsigned* h)
{
    uint32_t base = (uint32_t)(row * 128 + cg * 2);
    *(uint4*)(smp + swz(base))      = make_uint4(h[0],  h[1],  h[2],  h[3]);
    *(uint4*)(smp + swz(base + 16)) = make_uint4(h[4],  h[5],  h[6],  h[7]);
    *(uint4*)(smp + swz(base + 32)) = make_uint4(h[8],  h[9],  h[10], h[11]);
    *(uint4*)(smp + swz(base + 48)) = make_uint4(h[12], h[13], h[14], h[15]);
}

__device__ __forceinline__ void mma_stage_h(uint32_t asu, uint32_t bsu, int wm, int wn,
                                            int lane, float (*acc)[4][4])
{
    #pragma unroll
    for (int kk = 0; kk < 64; kk += 16) {
        unsigned A[4][4], Bf[4][2];
        uint32_t co = (uint32_t)((kk + ((lane >> 4) << 3)) * 2);
        #pragma unroll
        for (int im = 0; im < 4; im++) {
            uint32_t row = wm * 64 + im * 16 + (lane & 15);
            ldsm4(asu + swz(row * 128 + co), A[im][0], A[im][1], A[im][2], A[im][3]);
        }
        uint32_t cb = (uint32_t)((kk + (((lane >> 3) & 1) << 3)) * 2);
        #pragma unroll
        for (int p = 0; p < 2; p++) {
            uint32_t rb = wn * 32 + p * 16 + (lane & 7) + (((lane >> 4) & 1) << 3);
            ldsm4(bsu + swz(rb * 128 + cb), Bf[2*p][0], Bf[2*p][1], Bf[2*p+1][0], Bf[2*p+1][1]);
        }
        #pragma unroll
        for (int im = 0; im < 4; im++)
            #pragma unroll
            for (int in = 0; in < 4; in++)
                mmah(acc[im][in], A[im], Bf[in]);
    }
}

// ---------------------------------------------------------------------------
// small kernels
// ---------------------------------------------------------------------------
__global__ __launch_bounds__(256) void k_proj(const float* __restrict__ x1,
                                              const float* __restrict__ x2,
                                              const float* __restrict__ w)
{
    int warp = threadIdx.x >> 5, lane = threadIdx.x & 31;
    int row = blockIdx.x * 8 + warp;
    const float* x; const float* wv; float* o; int r;
    if (row < BB * NN) { x = x1; wv = w;      o = g_s1; r = row; }
    else               { x = x2; wv = w + DD; o = g_s2; r = row - BB * NN; }
    const float* xr = x + (size_t)r * DD;
    float acc = 0.f;
    #pragma unroll 4
    for (int i = lane; i < DD; i += 32) acc += xr[i] * wv[i];
    #pragma unroll
    for (int s = 16; s; s >>= 1) acc += __shfl_xor_sync(0xffffffffu, acc, s);
    if (lane == 0) o[r] = acc;
}

__global__ __launch_bounds__(256) void k_rowstats()
{
    const int r = blockIdx.x;
    const float* row = g_S + (size_t)r * MM;
    const int t = threadIdx.x;
    __shared__ float sm[256];
    float mx = NEGV;
    #pragma unroll 4
    for (int i = t; i < MM; i += 256) mx = fmaxf(mx, row[i]);
    sm[t] = mx; __syncthreads();
    for (int s = 128; s; s >>= 1) { if (t < s) sm[t] = fmaxf(sm[t], sm[t + s]); __syncthreads(); }
    mx = sm[0]; __syncthreads();
    float l = 0.f;
    #pragma unroll 4
    for (int i = t; i < MM; i += 256) l += __expf(row[i] - mx);
    sm[t] = l; __syncthreads();
    for (int s = 128; s; s >>= 1) { if (t < s) sm[t] += sm[t + s]; __syncthreads(); }
    if (t == 0) { g_rowM[r] = mx; g_rowIL[r] = 1.f / sm[0]; }
}

__global__ __launch_bounds__(256) void k_colpart(const int* __restrict__ x1_mask)
{
    const int b = blockIdx.z;
    const int chunk = blockIdx.y;
    const int m = blockIdx.x * 256 + threadIdx.x;
    const float* Sb = g_S + (size_t)b * NN * MM;
    float mx = NEGV, l = 0.f;
    const int n0 = chunk * (NN / NCHUNK);
    for (int n = n0; n < n0 + NN / NCHUNK; n++) {
        float v = x1_mask[b * NN + n] ? NEGV : Sb[(size_t)n * MM + m];
        float mn = fmaxf(mx, v);
        l = l * __expf(mx - mn) + __expf(v - mn);
        mx = mn;
    }
    g_pM[(b * NCHUNK + chunk) * MM + m] = mx;
    g_pL[(b * NCHUNK + chunk) * MM + m] = l;
}

__global__ __launch_bounds__(256) void k_colcomb()
{
    const int idx = blockIdx.x * 256 + threadIdx.x;
    const int b = idx / MM, m = idx % MM;
    float mx = NEGV;
    #pragma unroll
    for (int c = 0; c < NCHUNK; c++) mx = fmaxf(mx, g_pM[(b * NCHUNK + c) * MM + m]);
    float l = 0.f;
    #pragma unroll
    for (int c = 0; c < NCHUNK; c++)
        l += g_pL[(b * NCHUNK + c) * MM + m] * __expf(g_pM[(b * NCHUNK + c) * MM + m] - mx);
    g_colM[idx] = mx;
    g_colIL[idx] = 1.f / l;
}

// S := row_softmax(S) in place (runs after q2c consumed raw S)
__global__ __launch_bounds__(256) void k_pwrite()
{
    const int r = blockIdx.x;
    float* row = g_S + (size_t)r * MM;
    const float mx = g_rowM[r], il = g_rowIL[r];
    const int t = threadIdx.x;
    #pragma unroll
    for (int i = 0; i < 1; i++) {
        float4 v = *(float4*)(row + t * 4);
        v.x = __expf(v.x - mx) * il;
        v.y = __expf(v.y - mx) * il;
        v.z = __expf(v.z - mx) * il;
        v.w = __expf(v.w - mx) * il;
        *(float4*)(row + t * 4) = v;
    }
}

// ---------------------------------------------------------------------------
// K1: S = (x1*w3) @ x2^T + s1 + s2 + bias, mask  (bf16 3-term, occ-2)
// ---------------------------------------------------------------------------
__global__ __launch_bounds__(256, 2) void k_sim_t(const float* __restrict__ x1,
                                                  const float* __restrict__ x2,
                                                  const float* __restrict__ w,
                                                  const float* __restrict__ bias,
                                                  const int* __restrict__ x2_mask)
{
    float* wsm = (float*)(dsm + 4 * TILE_B);
    const int b = blockIdx.z, row0 = blockIdx.y * 128, col0 = blockIdx.x * 128;
    const int t = threadIdx.x, lane = t & 31, wid = t >> 5;
    const int wm = wid & 1, wn = wid >> 1;
    for (int i = t; i < DD; i += 256) wsm[i] = w[2 * DD + i];
    const float* Ag = x1 + ((size_t)b * NN + row0) * DD;
    const float* Bg = x2 + ((size_t)b * MM + col0) * DD;
    const int sr = t >> 1, scg = (t & 1) * 16;
    const uint32_t sb = (uint32_t)__cvta_generic_to_shared(dsm);
    float va[16], vb[16];
    float acc[4][4][4] = {};
    __syncthreads();
    #pragma unroll
    for (int q = 0; q < 4; q++) {
        float4 fa = *(const float4*)(Ag + (size_t)sr * DD + scg + 4 * q);
        float4 fb = *(const float4*)(Bg + (size_t)sr * DD + scg + 4 * q);
        va[4*q] = fa.x; va[4*q+1] = fa.y; va[4*q+2] = fa.z; va[4*q+3] = fa.w;
        vb[4*q] = fb.x; vb[4*q+1] = fb.y; vb[4*q+2] = fb.z; vb[4*q+3] = fb.w;
    }
    #pragma unroll
    for (int j = 0; j < 16; j++) va[j] *= wsm[scg + j];
    store16(dsm,          sr, scg, va);
    store16(dsm + TILE_B, sr, scg, vb);
    __syncthreads();
    const int NS = DD / 32;
    for (int s = 0; s < NS; s++) {
        const bool more = (s + 1 < NS);
        if (more) {
            const int k0 = (s + 1) * 32;
            #pragma unroll
            for (int q = 0; q < 4; q++) {
                float4 fa = *(const float4*)(Ag + (size_t)sr * DD + k0 + scg + 4 * q);
                float4 fb = *(const float4*)(Bg + (size_t)sr * DD + k0 + scg + 4 * q);
                va[4*q] = fa.x; va[4*q+1] = fa.y; va[4*q+2] = fa.z; va[4*q+3] = fa.w;
                vb[4*q] = fb.x; vb[4*q+1] = fb.y; vb[4*q+2] = fb.z; vb[4*q+3] = fb.w;
            }
            #pragma unroll
            for (int j = 0; j < 16; j++) va[j] *= wsm[(s + 1) * 32 + scg + j];
        }
        const uint32_t base = sb + (s & 1) * 2 * TILE_B;
        mma_stage(base, base + TILE_B, wm, wn, lane, acc);
        if (more) {
            char* nbuf = dsm + ((s + 1) & 1) * 2 * TILE_B;
            store16(nbuf,          sr, scg, va);
            store16(nbuf + TILE_B, sr, scg, vb);
        }
        __syncthreads();
    }
    const float biasv = *bias;
    #pragma unroll
    for (int im = 0; im < 4; im++) {
        int r = row0 + wm * 64 + im * 16 + (lane >> 2);
        float s1a = g_s1[b * NN + r], s1b = g_s1[b * NN + r + 8];
        #pragma unroll
        for (int in = 0; in < 4; in++) {
            int c = col0 + wn * 32 + in * 8 + 2 * (lane & 3);
            float s2a = g_s2[b * MM + c], s2b = g_s2[b * MM + c + 1];
            int m0 = x2_mask[b * MM + c], m1 = x2_mask[b * MM + c + 1];
            float* acf = acc[im][in];
            float2 o0, o1;
            o0.x = m0 ? NEGV : (acf[0] + s1a + s2a + biasv);
            o0.y = m1 ? NEGV : (acf[1] + s1a + s2b + biasv);
            o1.x = m0 ? NEGV : (acf[2] + s1b + s2a + biasv);
            o1.y = m1 ? NEGV : (acf[3] + s1b + s2b + biasv);
            *(float2*)&g_S[((size_t)b * NN + r) * MM + c]     = o0;
            *(float2*)&g_S[((size_t)b * NN + r + 8) * MM + c] = o1;
        }
    }
}

// ---------------------------------------------------------------------------
// K5: q2c = col_softmax(S)^T @ x1   (fp16 single-term, BK=64, occ-2)
// ---------------------------------------------------------------------------
__global__ __launch_bounds__(256, 2) void k_q2c_t(const float* __restrict__ x1,
                                                  const int* __restrict__ x1_mask)
{
    const int b = blockIdx.z, row0m = blockIdx.y * 128, col0 = blockIdx.x * 128;
    const int t = threadIdx.x, lane = t & 31, wid = t >> 5;
    const int wm = wid & 1, wn = wid >> 1;
    const float* Sb = g_S + (size_t)b * NN * MM;
    const float* Xb = x1 + (size_t)b * NN * DD;
    const int r_ = t & 127, kh2 = (t >> 7) * 32;
    const float cM = g_colM[b * MM + row0m + r_];
    const float cI = g_colIL[b * MM + row0m + r_];
    const uint32_t sb = (uint32_t)__cvta_generic_to_shared(dsm);
    unsigned ha[16], hb[16];
    float acc[4][4][4] = {};
    #pragma unroll
    for (int j = 0; j < 16; j++) {
        int n0 = kh2 + 2*j, n1 = n0 + 1;
        float s0 = x1_mask[b*NN + n0] ? NEGV : Sb[(size_t)n0 * MM + row0m + r_];
        float s1 = x1_mask[b*NN + n1] ? NEGV : Sb[(size_t)n1 * MM + row0m + r_];
        __half2 pa = __floats2half2_rn(__expf(s0 - cM) * cI, __expf(s1 - cM) * cI);
        __half2 pb = __floats2half2_rn(Xb[(size_t)n0 * DD + col0 + r_],
                                       Xb[(size_t)n1 * DD + col0 + r_]);
        ha[j] = *(unsigned*)&pa;
        hb[j] = *(unsigned*)&pb;
    }
    store32h(dsm,          r_, kh2, ha);
    store32h(dsm + TILE_B, r_, kh2, hb);
    __syncthreads();
    const int NS = NN / 64;
    for (int s = 0; s < NS; s++) {
        const bool more = (s + 1 < NS);
        if (more) {
            const int k0 = (s + 1) * 64;
            #pragma unroll
            for (int j = 0; j < 16; j++) {
                int n0 = k0 + kh2 + 2*j, n1 = n0 + 1;
                float s0 = x1_mask[b*NN + n0] ? NEGV : Sb[(size_t)n0 * MM + row0m + r_];
                float s1 = x1_mask[b*NN + n1] ? NEGV : Sb[(size_t)n1 * MM + row0m + r_];
                __half2 pa = __floats2half2_rn(__expf(s0 - cM) * cI, __expf(s1 - cM) * cI);
                __half2 pb = __floats2half2_rn(Xb[(size_t)n0 * DD + col0 + r_],
                                               Xb[(size_t)n1 * DD + col0 + r_]);
                ha[j] = *(unsigned*)&pa;
                hb[j] = *(unsigned*)&pb;
            }
        }
        const uint32_t base = sb + (s & 1) * 2 * TILE_B;
        mma_stage_h(base, base + TILE_B, wm, wn, lane, acc);
        if (more) {
            char* nbuf = dsm + ((s + 1) & 1) * 2 * TILE_B;
            store32h(nbuf,          r_, kh2, ha);
            store32h(nbuf + TILE_B, r_, kh2, hb);
        }
        __syncthreads();
    }
    #pragma unroll
    for (int im = 0; im < 4; im++) {
        int r = row0m + wm * 64 + im * 16 + (lane >> 2);
        #pragma unroll
        for (int in = 0; in < 4; in++) {
            int c = col0 + wn * 32 + in * 8 + 2 * (lane & 3);
            float* acf = acc[im][in];
            *(float2*)&g_q2c[((size_t)b * MM + r) * DD + c]     = make_float2(acf[0], acf[1]);
            *(float2*)&g_q2c[((size_t)b * MM + r + 8) * DD + c] = make_float2(acf[2], acf[3]);
        }
    }
}

// ---------------------------------------------------------------------------
// K4: Out = P @ Bmat   (fp16, BK=64, occ-2; P pre-written into g_S; useQ picks B)
// ---------------------------------------------------------------------------
__global__ __launch_bounds__(256, 2) void k_pv_t(const float* __restrict__ Bext,
                                                 float* __restrict__ Out, int useQ)
{
    const int b = blockIdx.z, row0 = blockIdx.y * 128, col0 = blockIdx.x * 128;
    const int t = threadIdx.x, lane = t & 31, wid = t >> 5;
    const int wm = wid & 1, wn = wid >> 1;
    const float* Pb = g_S + ((size_t)b * NN + row0) * MM;
    const float* Bb = (useQ ? (const float*)g_q2c : Bext) + (size_t)b * MM * DD;
    const int sr = t >> 1, skh = (t & 1) * 32;
    const int sd = t & 127, sseg = (t >> 7) * 32;
    const uint32_t sb = (uint32_t)__cvta_generic_to_shared(dsm);
    unsigned ha[16], hb[16];
    float acc[4][4][4] = {};
    #pragma unroll
    for (int q = 0; q < 8; q++) {
        float4 f = *(const float4*)(Pb + (size_t)sr * MM + skh + 4 * q);
        __half2 p0 = __floats2half2_rn(f.x, f.y);
        __half2 p1 = __floats2half2_rn(f.z, f.w);
        ha[2*q]   = *(unsigned*)&p0;
        ha[2*q+1] = *(unsigned*)&p1;
    }
    #pragma unroll
    for (int j = 0; j < 16; j++) {
        __half2 p = __floats2half2_rn(Bb[(size_t)(sseg + 2*j) * DD + col0 + sd],
                                      Bb[(size_t)(sseg + 2*j + 1) * DD + col0 + sd]);
        hb[j] = *(unsigned*)&p;
    }
    store32h(dsm,          sr, skh,  ha);
    store32h(dsm + TILE_B, sd, sseg, hb);
    __syncthreads();
    const int NS = MM / 64;
    for (int s = 0; s < NS; s++) {
        const bool more = (s + 1 < NS);
        if (more) {
            const int k0 = (s + 1) * 64;
            #pragma unroll
            for (int q = 0; q < 8; q++) {
                float4 f = *(const float4*)(Pb + (size_t)sr * MM + k0 + skh + 4 * q);
                __half2 p0 = __floats2half2_rn(f.x, f.y);
                __half2 p1 = __floats2half2_rn(f.z, f.w);
                ha[2*q]   = *(unsigned*)&p0;
                ha[2*q+1] = *(unsigned*)&p1;
            }
            #pragma unroll
            for (int j = 0; j < 16; j++) {
                __half2 p = __floats2half2_rn(Bb[(size_t)(k0 + sseg + 2*j) * DD + col0 + sd],
                                              Bb[(size_t)(k0 + sseg + 2*j + 1) * DD + col0 + sd]);
                hb[j] = *(unsigned*)&p;
            }
        }
        const uint32_t base = sb + (s & 1) * 2 * TILE_B;
        mma_stage_h(base, base + TILE_B, wm, wn, lane, acc);
        if (more) {
            char* nbuf = dsm + ((s + 1) & 1) * 2 * TILE_B;
            store32h(nbuf,          sr, skh,  ha);
            store32h(nbuf + TILE_B, sd, sseg, hb);
        }
        __syncthreads();
    }
    #pragma unroll
    for (int im = 0; im < 4; im++) {
        int r = row0 + wm * 64 + im * 16 + (lane >> 2);
        #pragma unroll
        for (int in = 0; in < 4; in++) {
            int c = col0 + wn * 32 + in * 8 + 2 * (lane & 3);
            float* acf = acc[im][in];
            *(float2*)&Out[((size_t)b * NN + r) * DD + c]     = make_float2(acf[0], acf[1]);
            *(float2*)&Out[((size_t)b * NN + r + 8) * DD + c] = make_float2(acf[2], acf[3]);
        }
    }
}

// ---------------------------------------------------------------------------
extern "C" void kernel_launch(void* const* d_in, const int* in_sizes, int n_in,
                              void* d_out, int out_size)
{
    const float* x1      = (const float*)d_in[0];
    const int*   x1_mask = (const int*)d_in[1];
    const float* x2      = (const float*)d_in[2];
    const int*   x2_mask = (const int*)d_in[3];
    const float* w       = (const float*)d_in[4];
    const float* bias    = (const float*)d_in[5];
    float*       out     = (float*)d_out;

    const int smem_sim = 4 * TILE_B + DD * 4;
    const int smem_gen = 4 * TILE_B;
    cudaFuncSetAttribute(k_sim_t, cudaFuncAttributeMaxDynamicSharedMemorySize, smem_sim);
    cudaFuncSetAttribute(k_q2c_t, cudaFuncAttributeMaxDynamicSharedMemorySize, smem_gen);
    cudaFuncSetAttribute(k_pv_t,  cudaFuncAttributeMaxDynamicSharedMemorySize, smem_gen);

    k_proj<<<(2 * BB * NN) / 8, 256>>>(x1, x2, w);

    dim3 gs(MM / 128, NN / 128, BB);
    k_sim_t<<<gs, 256, smem_sim>>>(x1, x2, w, bias, x2_mask);

    k_rowstats<<<BB * NN, 256>>>();
    k_colpart<<<dim3(MM / 256, NCHUNK, BB), 256>>>(x1_mask);
    k_colcomb<<<(BB * MM) / 256, 256>>>();

    dim3 gq(DD / 128, MM / 128, BB);
    k_q2c_t<<<gq, 256, smem_gen>>>(x1, x1_mask);     // consumes raw S

    k_pwrite<<<BB * NN, 256>>>();                    // S := P (fp32, in place)

    dim3 gp(DD / 128, NN / 128, BB);
    k_pv_t<<<gp, 256, smem_gen>>>(x2, out, 0);                          // attn_a
    k_pv_t<<<gp, 256, smem_gen>>>(nullptr, out + (size_t)BB * NN * DD, 1);  // attn_b
}

// round 17
// speedup vs baseline: 1.0795x; 1.0795x over previous
#include <cuda_runtime.h>
#include <cuda_bf16.h>
#include <cuda_fp16.h>
#include <stdint.h>
#include <math.h>

#define BB 16
#define NN 1024
#define MM 1024
#define DD 512
#define NEGV (-2e20f)
#define NCHUNK 16

// ---- scratch (static device memory; ~96.3MB, proven envelope) ----
__device__ float g_S[(size_t)BB * NN * MM];     // 64 MB masked logits
__device__ float g_q2c[(size_t)BB * MM * DD];   // 32 MB
__device__ float g_s1[BB * NN];
__device__ float g_s2[BB * MM];
__device__ float g_rowM[BB * NN];
__device__ float g_rowIL[BB * NN];
__device__ float g_colM[BB * MM];
__device__ float g_colIL[BB * MM];
__device__ float g_pM[BB * NCHUNK * MM];
__device__ float g_pL[BB * NCHUNK * MM];

#define TILE_B 16384
extern __shared__ char dsm[];

__device__ __forceinline__ uint32_t swz(uint32_t off) { return off ^ ((off >> 3) & 0x70u); }

__device__ __forceinline__ void ldsm4(uint32_t addr, unsigned &r0, unsigned &r1,
                                      unsigned &r2, unsigned &r3)
{
    asm volatile("ldmatrix.sync.aligned.m8n8.x4.shared.b16 {%0,%1,%2,%3}, [%4];"
                 : "=r"(r0), "=r"(r1), "=r"(r2), "=r"(r3) : "r"(addr));
}

__device__ __forceinline__ void mmah(float* c, const unsigned* a, const unsigned* b)
{
    asm volatile("mma.sync.aligned.m16n8k16.row.col.f32.f16.f16.f32 "
                 "{%0,%1,%2,%3},{%4,%5,%6,%7},{%8,%9},{%0,%1,%2,%3};"
                 : "+f"(c[0]), "+f"(c[1]), "+f"(c[2]), "+f"(c[3])
                 : "r"(a[0]), "r"(a[1]), "r"(a[2]), "r"(a[3]), "r"(b[0]), "r"(b[1]));
}

// ---- fp16 helpers (BK=64; row = 64 fp16 = 128B) ----
__device__ __forceinline__ void store32h(char* smp, int row, int cg, const unsigned* h)
{
    uint32_t base = (uint32_t)(row * 128 + cg * 2);
    *(uint4*)(smp + swz(base))      = make_uint4(h[0],  h[1],  h[2],  h[3]);
    *(uint4*)(smp + swz(base + 16)) = make_uint4(h[4],  h[5],  h[6],  h[7]);
    *(uint4*)(smp + swz(base + 32)) = make_uint4(h[8],  h[9],  h[10], h[11]);
    *(uint4*)(smp + swz(base + 48)) = make_uint4(h[12], h[13], h[14], h[15]);
}

__device__ __forceinline__ void mma_stage_h(uint32_t asu, uint32_t bsu, int wm, int wn,
                                            int lane, float (*acc)[4][4])
{
    #pragma unroll
    for (int kk = 0; kk < 64; kk += 16) {
        unsigned A[4][4], Bf[4][2];
        uint32_t co = (uint32_t)((kk + ((lane >> 4) << 3)) * 2);
        #pragma unroll
        for (int im = 0; im < 4; im++) {
            uint32_t row = wm * 64 + im * 16 + (lane & 15);
            ldsm4(asu + swz(row * 128 + co), A[im][0], A[im][1], A[im][2], A[im][3]);
        }
        uint32_t cb = (uint32_t)((kk + (((lane >> 3) & 1) << 3)) * 2);
        #pragma unroll
        for (int p = 0; p < 2; p++) {
            uint32_t rb = wn * 32 + p * 16 + (lane & 7) + (((lane >> 4) & 1) << 3);
            ldsm4(bsu + swz(rb * 128 + cb), Bf[2*p][0], Bf[2*p][1], Bf[2*p+1][0], Bf[2*p+1][1]);
        }
        #pragma unroll
        for (int im = 0; im < 4; im++)
            #pragma unroll
            for (int in = 0; in < 4; in++)
                mmah(acc[im][in], A[im], Bf[in]);
    }
}

// ---------------------------------------------------------------------------
// small kernels (unchanged from R14)
// ---------------------------------------------------------------------------
__global__ __launch_bounds__(256) void k_proj(const float* __restrict__ x1,
                                              const float* __restrict__ x2,
                                              const float* __restrict__ w)
{
    int warp = threadIdx.x >> 5, lane = threadIdx.x & 31;
    int row = blockIdx.x * 8 + warp;
    const float* x; const float* wv; float* o; int r;
    if (row < BB * NN) { x = x1; wv = w;      o = g_s1; r = row; }
    else               { x = x2; wv = w + DD; o = g_s2; r = row - BB * NN; }
    const float* xr = x + (size_t)r * DD;
    float acc = 0.f;
    #pragma unroll 4
    for (int i = lane; i < DD; i += 32) acc += xr[i] * wv[i];
    #pragma unroll
    for (int s = 16; s; s >>= 1) acc += __shfl_xor_sync(0xffffffffu, acc, s);
    if (lane == 0) o[r] = acc;
}

__global__ __launch_bounds__(256) void k_rowstats()
{
    const int r = blockIdx.x;
    const float* row = g_S + (size_t)r * MM;
    const int t = threadIdx.x;
    __shared__ float sm[256];
    float mx = NEGV;
    #pragma unroll 4
    for (int i = t; i < MM; i += 256) mx = fmaxf(mx, row[i]);
    sm[t] = mx; __syncthreads();
    for (int s = 128; s; s >>= 1) { if (t < s) sm[t] = fmaxf(sm[t], sm[t + s]); __syncthreads(); }
    mx = sm[0]; __syncthreads();
    float l = 0.f;
    #pragma unroll 4
    for (int i = t; i < MM; i += 256) l += __expf(row[i] - mx);
    sm[t] = l; __syncthreads();
    for (int s = 128; s; s >>= 1) { if (t < s) sm[t] += sm[t + s]; __syncthreads(); }
    if (t == 0) { g_rowM[r] = mx; g_rowIL[r] = 1.f / sm[0]; }
}

__global__ __launch_bounds__(256) void k_colpart(const int* __restrict__ x1_mask)
{
    const int b = blockIdx.z;
    const int chunk = blockIdx.y;
    const int m = blockIdx.x * 256 + threadIdx.x;
    const float* Sb = g_S + (size_t)b * NN * MM;
    float mx = NEGV, l = 0.f;
    const int n0 = chunk * (NN / NCHUNK);
    for (int n = n0; n < n0 + NN / NCHUNK; n++) {
        float v = x1_mask[b * NN + n] ? NEGV : Sb[(size_t)n * MM + m];
        float mn = fmaxf(mx, v);
        l = l * __expf(mx - mn) + __expf(v - mn);
        mx = mn;
    }
    g_pM[(b * NCHUNK + chunk) * MM + m] = mx;
    g_pL[(b * NCHUNK + chunk) * MM + m] = l;
}

__global__ __launch_bounds__(256) void k_colcomb()
{
    const int idx = blockIdx.x * 256 + threadIdx.x;
    const int b = idx / MM, m = idx % MM;
    float mx = NEGV;
    #pragma unroll
    for (int c = 0; c < NCHUNK; c++) mx = fmaxf(mx, g_pM[(b * NCHUNK + c) * MM + m]);
    float l = 0.f;
    #pragma unroll
    for (int c = 0; c < NCHUNK; c++)
        l += g_pL[(b * NCHUNK + c) * MM + m] * __expf(g_pM[(b * NCHUNK + c) * MM + m] - mx);
    g_colM[idx] = mx;
    g_colIL[idx] = 1.f / l;
}

// ---------------------------------------------------------------------------
// K1: S = (x1*w3) @ x2^T + s1 + s2 + bias, mask  (fp16 single-term, BK=64)
// ---------------------------------------------------------------------------
__global__ __launch_bounds__(256, 1) void k_sim_t(const float* __restrict__ x1,
                                                  const float* __restrict__ x2,
                                                  const float* __restrict__ w,
                                                  const float* __restrict__ bias,
                                                  const int* __restrict__ x2_mask)
{
    float* wsm = (float*)(dsm + 4 * TILE_B);
    const int b = blockIdx.z, row0 = blockIdx.y * 128, col0 = blockIdx.x * 128;
    const int t = threadIdx.x, lane = t & 31, wid = t >> 5;
    const int wm = wid & 1, wn = wid >> 1;
    for (int i = t; i < DD; i += 256) wsm[i] = w[2 * DD + i];
    const float* Ag = x1 + ((size_t)b * NN + row0) * DD;
    const float* Bg = x2 + ((size_t)b * MM + col0) * DD;
    const int sr = t >> 1, skh = (t & 1) * 32;       // row 0..127, 32 k per thread
    const uint32_t sb = (uint32_t)__cvta_generic_to_shared(dsm);
    unsigned ha[16], hb[16];
    float acc[4][4][4] = {};
    __syncthreads();                                 // wsm ready
    #pragma unroll
    for (int q = 0; q < 8; q++) {
        float4 fa = *(const float4*)(Ag + (size_t)sr * DD + skh + 4 * q);
        float4 fb = *(const float4*)(Bg + (size_t)sr * DD + skh + 4 * q);
        float4 fw = *(const float4*)(wsm + skh + 4 * q);
        __half2 a0 = __floats2half2_rn(fa.x * fw.x, fa.y * fw.y);
        __half2 a1 = __floats2half2_rn(fa.z * fw.z, fa.w * fw.w);
        __half2 b0 = __floats2half2_rn(fb.x, fb.y);
        __half2 b1 = __floats2half2_rn(fb.z, fb.w);
        ha[2*q]   = *(unsigned*)&a0;
        ha[2*q+1] = *(unsigned*)&a1;
        hb[2*q]   = *(unsigned*)&b0;
        hb[2*q+1] = *(unsigned*)&b1;
    }
    store32h(dsm,          sr, skh, ha);
    store32h(dsm + TILE_B, sr, skh, hb);
    __syncthreads();
    const int NS = DD / 64;                          // 8
    for (int s = 0; s < NS; s++) {
        const bool more = (s + 1 < NS);
        if (more) {
            const int k0 = (s + 1) * 64;
            #pragma unroll
            for (int q = 0; q < 8; q++) {
                float4 fa = *(const float4*)(Ag + (size_t)sr * DD + k0 + skh + 4 * q);
                float4 fb = *(const float4*)(Bg + (size_t)sr * DD + k0 + skh + 4 * q);
                float4 fw = *(const float4*)(wsm + k0 + skh + 4 * q);
                __half2 a0 = __floats2half2_rn(fa.x * fw.x, fa.y * fw.y);
                __half2 a1 = __floats2half2_rn(fa.z * fw.z, fa.w * fw.w);
                __half2 b0 = __floats2half2_rn(fb.x, fb.y);
                __half2 b1 = __floats2half2_rn(fb.z, fb.w);
                ha[2*q]   = *(unsigned*)&a0;
                ha[2*q+1] = *(unsigned*)&a1;
                hb[2*q]   = *(unsigned*)&b0;
                hb[2*q+1] = *(unsigned*)&b1;
            }
        }
        const uint32_t base = sb + (s & 1) * 2 * TILE_B;
        mma_stage_h(base, base + TILE_B, wm, wn, lane, acc);
        if (more) {
            char* nbuf = dsm + ((s + 1) & 1) * 2 * TILE_B;
            store32h(nbuf,          sr, skh, ha);
            store32h(nbuf + TILE_B, sr, skh, hb);
        }
        __syncthreads();
    }
    const float biasv = *bias;
    #pragma unroll
    for (int im = 0; im < 4; im++) {
        int r = row0 + wm * 64 + im * 16 + (lane >> 2);
        float s1a = g_s1[b * NN + r], s1b = g_s1[b * NN + r + 8];
        #pragma unroll
        for (int in = 0; in < 4; in++) {
            int c = col0 + wn * 32 + in * 8 + 2 * (lane & 3);
            float s2a = g_s2[b * MM + c], s2b = g_s2[b * MM + c + 1];
            int m0 = x2_mask[b * MM + c], m1 = x2_mask[b * MM + c + 1];
            float* acf = acc[im][in];
            float2 o0, o1;
            o0.x = m0 ? NEGV : (acf[0] + s1a + s2a + biasv);
            o0.y = m1 ? NEGV : (acf[1] + s1a + s2b + biasv);
            o1.x = m0 ? NEGV : (acf[2] + s1b + s2a + biasv);
            o1.y = m1 ? NEGV : (acf[3] + s1b + s2b + biasv);
            *(float2*)&g_S[((size_t)b * NN + r) * MM + c]     = o0;
            *(float2*)&g_S[((size_t)b * NN + r + 8) * MM + c] = o1;
        }
    }
}

// ---------------------------------------------------------------------------
// K5: q2c = col_softmax(S)^T @ x1   (fp16 single-term, BK=64, unchanged R14)
// ---------------------------------------------------------------------------
__global__ __launch_bounds__(256, 1) void k_q2c_t(const float* __restrict__ x1,
                                                  const int* __restrict__ x1_mask)
{
    const int b = blockIdx.z, row0m = blockIdx.y * 128, col0 = blockIdx.x * 128;
    const int t = threadIdx.x, lane = t & 31, wid = t >> 5;
    const int wm = wid & 1, wn = wid >> 1;
    const float* Sb = g_S + (size_t)b * NN * MM;
    const float* Xb = x1 + (size_t)b * NN * DD;
    const int r_ = t & 127, kh2 = (t >> 7) * 32;
    const float cM = g_colM[b * MM + row0m + r_];
    const float cI = g_colIL[b * MM + row0m + r_];
    const uint32_t sb = (uint32_t)__cvta_generic_to_shared(dsm);
    unsigned ha[16], hb[16];
    float acc[4][4][4] = {};
    #pragma unroll
    for (int j = 0; j < 16; j++) {
        int n0 = kh2 + 2*j, n1 = n0 + 1;
        float s0 = x1_mask[b*NN + n0] ? NEGV : Sb[(size_t)n0 * MM + row0m + r_];
        float s1 = x1_mask[b*NN + n1] ? NEGV : Sb[(size_t)n1 * MM + row0m + r_];
        __half2 pa = __floats2half2_rn(__expf(s0 - cM) * cI, __expf(s1 - cM) * cI);
        __half2 pb = __floats2half2_rn(Xb[(size_t)n0 * DD + col0 + r_],
                                       Xb[(size_t)n1 * DD + col0 + r_]);
        ha[j] = *(unsigned*)&pa;
        hb[j] = *(unsigned*)&pb;
    }
    store32h(dsm,          r_, kh2, ha);
    store32h(dsm + TILE_B, r_, kh2, hb);
    __syncthreads();
    const int NS = NN / 64;
    for (int s = 0; s < NS; s++) {
        const bool more = (s + 1 < NS);
        if (more) {
            const int k0 = (s + 1) * 64;
            #pragma unroll
            for (int j = 0; j < 16; j++) {
                int n0 = k0 + kh2 + 2*j, n1 = n0 + 1;
                float s0 = x1_mask[b*NN + n0] ? NEGV : Sb[(size_t)n0 * MM + row0m + r_];
                float s1 = x1_mask[b*NN + n1] ? NEGV : Sb[(size_t)n1 * MM + row0m + r_];
                __half2 pa = __floats2half2_rn(__expf(s0 - cM) * cI, __expf(s1 - cM) * cI);
                __half2 pb = __floats2half2_rn(Xb[(size_t)n0 * DD + col0 + r_],
                                               Xb[(size_t)n1 * DD + col0 + r_]);
                ha[j] = *(unsigned*)&pa;
                hb[j] = *(unsigned*)&pb;
            }
        }
        const uint32_t base = sb + (s & 1) * 2 * TILE_B;
        mma_stage_h(base, base + TILE_B, wm, wn, lane, acc);
        if (more) {
            char* nbuf = dsm + ((s + 1) & 1) * 2 * TILE_B;
            store32h(nbuf,          r_, kh2, ha);
            store32h(nbuf + TILE_B, r_, kh2, hb);
        }
        __syncthreads();
    }
    #pragma unroll
    for (int im = 0; im < 4; im++) {
        int r = row0m + wm * 64 + im * 16 + (lane >> 2);
        #pragma unroll
        for (int in = 0; in < 4; in++) {
            int c = col0 + wn * 32 + in * 8 + 2 * (lane & 3);
            float* acf = acc[im][in];
            *(float2*)&g_q2c[((size_t)b * MM + r) * DD + c]     = make_float2(acf[0], acf[1]);
            *(float2*)&g_q2c[((size_t)b * MM + r + 8) * DD + c] = make_float2(acf[2], acf[3]);
        }
    }
}

// ---------------------------------------------------------------------------
// K4: FUSED  attn_a = P @ x2  AND  attn_b = P @ q2c   (unchanged R14)
// ---------------------------------------------------------------------------
__global__ __launch_bounds__(256, 1) void k_pv2_t(const float* __restrict__ x2,
                                                  float* __restrict__ OutA,
                                                  float* __restrict__ OutB)
{
    const int b = blockIdx.z, row0 = blockIdx.y * 128, col0 = blockIdx.x * 128;
    const int t = threadIdx.x, lane = t & 31, wid = t >> 5;
    const int wm = wid & 1, wn = wid >> 1;
    const float* Sb  = g_S + ((size_t)b * NN + row0) * MM;
    const float* Bb1 = x2 + (size_t)b * MM * DD;
    const float* Bb2 = (const float*)g_q2c + (size_t)b * MM * DD;
    const int sr = t >> 1, skh = (t & 1) * 32;
    const int sd = t & 127, sseg = (t >> 7) * 32;
    const float rM = g_rowM[b * NN + row0 + sr];
    const float rI = g_rowIL[b * NN + row0 + sr];
    const uint32_t sb = (uint32_t)__cvta_generic_to_shared(dsm);
    unsigned ha[16], hb1[16], hb2[16];
    float acc1[4][4][4] = {};
    float acc2[4][4][4] = {};
    #pragma unroll
    for (int q = 0; q < 8; q++) {
        float4 f = *(const float4*)(Sb + (size_t)sr * MM + skh + 4 * q);
        __half2 p0 = __floats2half2_rn(__expf(f.x - rM) * rI, __expf(f.y - rM) * rI);
        __half2 p1 = __floats2half2_rn(__expf(f.z - rM) * rI, __expf(f.w - rM) * rI);
        ha[2*q]   = *(unsigned*)&p0;
        ha[2*q+1] = *(unsigned*)&p1;
    }
    #pragma unroll
    for (int j = 0; j < 16; j++) {
        __half2 p1 = __floats2half2_rn(Bb1[(size_t)(sseg + 2*j) * DD + col0 + sd],
                                       Bb1[(size_t)(sseg + 2*j + 1) * DD + col0 + sd]);
        __half2 p2 = __floats2half2_rn(Bb2[(size_t)(sseg + 2*j) * DD + col0 + sd],
                                       Bb2[(size_t)(sseg + 2*j + 1) * DD + col0 + sd]);
        hb1[j] = *(unsigned*)&p1;
        hb2[j] = *(unsigned*)&p2;
    }
    store32h(dsm,              sr, skh,  ha);
    store32h(dsm + TILE_B,     sd, sseg, hb1);
    store32h(dsm + 2 * TILE_B, sd, sseg, hb2);
    __syncthreads();
    const int NS = MM / 64;
    for (int s = 0; s < NS; s++) {
        const bool more = (s + 1 < NS);
        if (more) {
            const int k0 = (s + 1) * 64;
            #pragma unroll
            for (int q = 0; q < 8; q++) {
                float4 f = *(const float4*)(Sb + (size_t)sr * MM + k0 + skh + 4 * q);
                __half2 p0 = __floats2half2_rn(__expf(f.x - rM) * rI, __expf(f.y - rM) * rI);
                __half2 p1 = __floats2half2_rn(__expf(f.z - rM) * rI, __expf(f.w - rM) * rI);
                ha[2*q]   = *(unsigned*)&p0;
                ha[2*q+1] = *(unsigned*)&p1;
            }
            #pragma unroll
            for (int j = 0; j < 16; j++) {
                __half2 p1 = __floats2half2_rn(Bb1[(size_t)(k0 + sseg + 2*j) * DD + col0 + sd],
                                               Bb1[(size_t)(k0 + sseg + 2*j + 1) * DD + col0 + sd]);
                __half2 p2 = __floats2half2_rn(Bb2[(size_t)(k0 + sseg + 2*j) * DD + col0 + sd],
                                               Bb2[(size_t)(k0 + sseg + 2*j + 1) * DD + col0 + sd]);
                hb1[j] = *(unsigned*)&p1;
                hb2[j] = *(unsigned*)&p2;
            }
        }
        const uint32_t base = sb + (s & 1) * 3 * TILE_B;
        mma_stage_h(base, base + TILE_B,     wm, wn, lane, acc1);
        mma_stage_h(base, base + 2 * TILE_B, wm, wn, lane, acc2);
        if (more) {
            char* nbuf = dsm + ((s + 1) & 1) * 3 * TILE_B;
            store32h(nbuf,              sr, skh,  ha);
            store32h(nbuf + TILE_B,     sd, sseg, hb1);
            store32h(nbuf + 2 * TILE_B, sd, sseg, hb2);
        }
        __syncthreads();
    }
    #pragma unroll
    for (int im = 0; im < 4; im++) {
        int r = row0 + wm * 64 + im * 16 + (lane >> 2);
        #pragma unroll
        for (int in = 0; in < 4; in++) {
            int c = col0 + wn * 32 + in * 8 + 2 * (lane & 3);
            float* a1 = acc1[im][in];
            float* a2 = acc2[im][in];
            *(float2*)&OutA[((size_t)b * NN + r) * DD + c]     = make_float2(a1[0], a1[1]);
            *(float2*)&OutA[((size_t)b * NN + r + 8) * DD + c] = make_float2(a1[2], a1[3]);
            *(float2*)&OutB[((size_t)b * NN + r) * DD + c]     = make_float2(a2[0], a2[1]);
            *(float2*)&OutB[((size_t)b * NN + r + 8) * DD + c] = make_float2(a2[2], a2[3]);
        }
    }
}

// ---------------------------------------------------------------------------
extern "C" void kernel_launch(void* const* d_in, const int* in_sizes, int n_in,
                              void* d_out, int out_size)
{
    const float* x1      = (const float*)d_in[0];
    const int*   x1_mask = (const int*)d_in[1];
    const float* x2      = (const float*)d_in[2];
    const int*   x2_mask = (const int*)d_in[3];
    const float* w       = (const float*)d_in[4];
    const float* bias    = (const float*)d_in[5];
    float*       out     = (float*)d_out;

    const int smem_sim = 4 * TILE_B + DD * 4;
    const int smem_gen = 4 * TILE_B;
    const int smem_pv2 = 6 * TILE_B;
    cudaFuncSetAttribute(k_sim_t, cudaFuncAttributeMaxDynamicSharedMemorySize, smem_sim);
    cudaFuncSetAttribute(k_q2c_t, cudaFuncAttributeMaxDynamicSharedMemorySize, smem_gen);
    cudaFuncSetAttribute(k_pv2_t, cudaFuncAttributeMaxDynamicSharedMemorySize, smem_pv2);

    k_proj<<<(2 * BB * NN) / 8, 256>>>(x1, x2, w);

    dim3 gs(MM / 128, NN / 128, BB);
    k_sim_t<<<gs, 256, smem_sim>>>(x1, x2, w, bias, x2_mask);

    k_rowstats<<<BB * NN, 256>>>();
    k_colpart<<<dim3(MM / 256, NCHUNK, BB), 256>>>(x1_mask);
    k_colcomb<<<(BB * MM) / 256, 256>>>();

    dim3 gq(DD / 128, MM / 128, BB);
    k_q2c_t<<<gq, 256, smem_gen>>>(x1, x1_mask);     // q2c first

    dim3 gp(DD / 128, NN / 128, BB);
    k_pv2_t<<<gp, 256, smem_pv2>>>(x2, out, out + (size_t)BB * NN * DD);  // attn_a + attn_b
}